// round 11
// baseline (speedup 1.0000x reference)
#include <cuda_runtime.h>
#include <cuda_fp16.h>
#include <cstdint>

#define Bn   8
#define CHn  7
#define Hn   256
#define Wn   256
#define NBR  6
#define C1   64
#define PX   4

#define CTAS_PER_BRANCH 1024
#define ITERS           8      // 1024 CTAs * 4 warps * 16 px * 8 iters = 524288 px

// Scratch for the "combined" (B,7,H,W) tensor between the two kernels.
__device__ float g_comb[Bn * CHn * Hn * Wn];

__device__ __forceinline__ uint32_t smem_u32(const void* p) {
    uint32_t a;
    asm("{ .reg .u64 t; cvta.to.shared.u64 t, %1; cvt.u32.u64 %0, t; }" : "=r"(a) : "l"(p));
    return a;
}
__device__ __forceinline__ unsigned packh2(float lo, float hi) {
    __half2 h = __floats2half2_rn(lo, hi);
    return *reinterpret_cast<unsigned*>(&h);
}
__device__ __forceinline__ void ldmatrix_x4(uint32_t r[4], uint32_t addr) {
    asm volatile("ldmatrix.sync.aligned.m8n8.x4.shared.b16 {%0,%1,%2,%3}, [%4];"
                 : "=r"(r[0]), "=r"(r[1]), "=r"(r[2]), "=r"(r[3]) : "r"(addr));
}
__device__ __forceinline__ void ldmatrix_x2(uint32_t r[2], uint32_t addr) {
    asm volatile("ldmatrix.sync.aligned.m8n8.x2.shared.b16 {%0,%1}, [%2];"
                 : "=r"(r[0]), "=r"(r[1]) : "r"(addr));
}
__device__ __forceinline__ void mma16816(float c[4], const uint32_t a[4], const uint32_t b[2]) {
    asm volatile(
        "mma.sync.aligned.m16n8k16.row.col.f32.f16.f16.f32 "
        "{%0,%1,%2,%3}, {%4,%5,%6,%7}, {%8,%9}, {%0,%1,%2,%3};"
        : "+f"(c[0]), "+f"(c[1]), "+f"(c[2]), "+f"(c[3])
        : "r"(a[0]), "r"(a[1]), "r"(a[2]), "r"(a[3]), "r"(b[0]), "r"(b[1]));
}

// ---------------------------------------------------------------------------
// Branch kernel: warp-level HMMA implicit GEMM.
// A[16 px, 32 k] fp16: k0-8 base taps, k9 = 1.0 (bias lane), k10-15 = 0,
//                      k16-24 check taps, k25-31 = 0.
// B[64 ch, 32 k] fp16: k0-8 W1 base taps, k9 = b1[c], k16-24 W1 check taps.
// D fp32. Epilogue: relu, tree dot w2, quad-reduce, +b2, sigmoid, weight, store.
// Row stride 40 halves (80B): conflict-free ldmatrix. A double-buffered.
// ---------------------------------------------------------------------------
__global__ __launch_bounds__(128) void branch_kernel(
    const float* __restrict__ x,
    const float* __restrict__ W1, const float* __restrict__ b1,
    const float* __restrict__ W2, const float* __restrict__ b2)
{
    __shared__ __half Bs[C1 * 40];           // 5120 B
    __shared__ __half As[4][2][16 * 40];     // 4 warps x 2 buffers x 1280 B
    __shared__ float  w2s[C1];
    __shared__ float  sb2v;

    const int tid  = threadIdx.x;
    const int warp = tid >> 5;
    const int lane = tid & 31;
    const int n    = blockIdx.y;
    const int base_ic = (n < 3) ? 0 : 1;
    const int srcch   = (n < 3) ? n : n + 1;

    // ---- stage B (reordered, fp16) + w2 + b2 ----
    for (int i = tid; i < C1 * 40; i += 128) Bs[i] = __ushort_as_half(0);
    __syncthreads();
    for (int i = tid; i < C1 * 9; i += 128) {
        int c = i / 9, k = i % 9;
        Bs[c * 40 + k]      = __float2half_rn(W1[(((n * C1 + c) * 2 + base_ic) * 9) + k]);
        Bs[c * 40 + 16 + k] = __float2half_rn(W1[(((n * C1 + c) * 2 + (1 - base_ic)) * 9) + k]);
    }
    for (int c = tid; c < C1; c += 128) {
        Bs[c * 40 + 9] = __float2half_rn(b1[n * C1 + c]);
        w2s[c] = W2[n * C1 + c];
    }
    if (tid == 0) sb2v = b2[n];
    __syncthreads();

    // ---- load B fragments into registers (kept for whole kernel) ----
    uint32_t bf[8][2][2];
    {
        const uint32_t bbase = smem_u32(Bs);
        #pragma unroll
        for (int j = 0; j < 8; j++)
            #pragma unroll
            for (int s = 0; s < 2; s++) {
                int row = 8 * j + (lane & 7);
                uint32_t addr = bbase + (uint32_t)(row * 40 + s * 16) * 2
                              + (uint32_t)(((lane >> 3) & 1) * 16);
                ldmatrix_x2(bf[j][s], addr);
            }
    }
    // per-thread w2 values for owned columns
    float w2a[8], w2b[8];
    #pragma unroll
    for (int j = 0; j < 8; j++) {
        int n0 = 8 * j + 2 * (lane & 3);
        w2a[j] = w2s[n0];
        w2b[j] = w2s[n0 + 1];
    }
    const float my_b2 = sb2v;

    for (int it = 0; it < ITERS; it++) {
        const int pixbase = ((blockIdx.x + it * CTAS_PER_BRANCH) * 4 + warp) * 16;
        const int buf = it & 1;
        const uint32_t abase = smem_u32(&As[warp][buf][0]);

        // ---- im2col: 2 threads per pixel (even: base ch, odd: check ch) ----
        const int p   = lane >> 1;
        const int pix = pixbase + p;
        const int b   = pix >> 16;
        const int hh0 = (pix >> 8) & 255;
        const int ww0 = pix & 255;
        const int ch  = (lane & 1) ? srcch : 3;
        const float* xs = x + ((size_t)(b * CHn + ch) << 16);

        // warp-uniform interior test: tile = one 16-px row segment
        const int tile_w = (pixbase >> 4) & 15;
        const bool interior = (hh0 >= 1) && (hh0 <= 254) && (tile_w >= 1) && (tile_w <= 14);

        float win[9];
        if (interior) {
            const float* pr = xs + (hh0 - 1) * Wn + (ww0 - 1);
            win[0] = __ldg(pr);          win[1] = __ldg(pr + 1);          win[2] = __ldg(pr + 2);
            win[3] = __ldg(pr + Wn);     win[4] = __ldg(pr + Wn + 1);     win[5] = __ldg(pr + Wn + 2);
            win[6] = __ldg(pr + 2 * Wn); win[7] = __ldg(pr + 2 * Wn + 1); win[8] = __ldg(pr + 2 * Wn + 2);
        } else {
            #pragma unroll
            for (int r = 0; r < 3; r++) {
                int hh = hh0 - 1 + r;
                bool hok = (hh >= 0) && (hh < Hn);
                #pragma unroll
                for (int cc = 0; cc < 3; cc++) {
                    int ww = ww0 - 1 + cc;
                    bool ok = hok && (ww >= 0) && (ww < Wn);
                    win[r * 3 + cc] = ok ? __ldg(&xs[hh * Wn + ww]) : 0.f;
                }
            }
        }

        unsigned hv0 = packh2(win[0], win[1]);
        unsigned hv1 = packh2(win[2], win[3]);
        unsigned hv2 = packh2(win[4], win[5]);
        unsigned hv3 = packh2(win[6], win[7]);
        unsigned hv4 = packh2(win[8], (lane & 1) ? 0.f : 1.0f);  // even gets bias lane k9

        {
            __half* Arow = &As[warp][buf][p * 40 + (lane & 1) * 16];
            *reinterpret_cast<uint4*>(Arow)     = make_uint4(hv0, hv1, hv2, hv3);
            *reinterpret_cast<uint4*>(Arow + 8) = make_uint4(hv4, 0u, 0u, 0u);
        }
        __syncwarp();

        // center values via shuffle (producer: lane 2*row+{0,1})
        const int g = lane >> 2;
        float cenC0 = __shfl_sync(0xFFFFFFFFu, win[4], (g << 1) | 1);
        float cenC1 = __shfl_sync(0xFFFFFFFFu, win[4], ((g + 8) << 1) | 1);
        float cenB0 = 0.f, cenB1 = 0.f;
        if (n == 0) {
            cenB0 = __shfl_sync(0xFFFFFFFFu, win[4], g << 1);
            cenB1 = __shfl_sync(0xFFFFFFFFu, win[4], (g + 8) << 1);
        }

        // ---- A fragments ----
        uint32_t a0[4], a1[4];
        {
            int row = lane & 15;
            uint32_t addr = abase + (uint32_t)(row * 40) * 2 + (uint32_t)((lane >> 4) * 16);
            ldmatrix_x4(a0, addr);        // k 0..15
            ldmatrix_x4(a1, addr + 32);   // k 16..31
        }

        // ---- 16 HMMA ----
        float c[8][4];
        #pragma unroll
        for (int j = 0; j < 8; j++) {
            c[j][0] = c[j][1] = c[j][2] = c[j][3] = 0.f;
            mma16816(c[j], a0, bf[j][0]);
            mma16816(c[j], a1, bf[j][1]);
        }

        // ---- epilogue: relu + w2 dot, 8 independent 4-deep chains ----
        float pa0 = 0.f, pa1 = 0.f, qa0 = 0.f, qa1 = 0.f;
        float pb0 = 0.f, pb1 = 0.f, qb0 = 0.f, qb1 = 0.f;
        #pragma unroll
        for (int j = 0; j < 8; j++) {
            float r0 = fmaxf(c[j][0], 0.f), r1 = fmaxf(c[j][1], 0.f);
            float r2 = fmaxf(c[j][2], 0.f), r3 = fmaxf(c[j][3], 0.f);
            if (j & 1) {
                pa1 = fmaf(w2a[j], r0, pa1); qa1 = fmaf(w2b[j], r1, qa1);
                pb1 = fmaf(w2a[j], r2, pb1); qb1 = fmaf(w2b[j], r3, qb1);
            } else {
                pa0 = fmaf(w2a[j], r0, pa0); qa0 = fmaf(w2b[j], r1, qa0);
                pb0 = fmaf(w2a[j], r2, pb0); qb0 = fmaf(w2b[j], r3, qb0);
            }
        }
        float simA = (pa0 + qa0) + (pa1 + qa1);
        float simB = (pb0 + qb0) + (pb1 + qb1);
        simA += __shfl_xor_sync(0xFFFFFFFFu, simA, 1);
        simB += __shfl_xor_sync(0xFFFFFFFFu, simB, 1);
        simA += __shfl_xor_sync(0xFFFFFFFFu, simA, 2);
        simB += __shfl_xor_sync(0xFFFFFFFFu, simB, 2);

        if ((lane & 3) == 0) {
            int pixA = pixbase + g;
            int pixB = pixbase + g + 8;
            float resA = cenC0 / (1.f + __expf(-(simA + my_b2)));
            float resB = cenC1 / (1.f + __expf(-(simB + my_b2)));
            int bA = pixA >> 16, hwA = pixA & 65535;
            int bB = pixB >> 16, hwB = pixB & 65535;
            g_comb[((size_t)(bA * CHn + srcch) << 16) + hwA] = resA;
            g_comb[((size_t)(bB * CHn + srcch) << 16) + hwB] = resB;
            if (n == 0) {
                g_comb[((size_t)(bA * CHn + 3) << 16) + hwA] = cenB0;
                g_comb[((size_t)(bB * CHn + 3) << 16) + hwB] = cenB1;
            }
        }
    }
}

// ---------------------------------------------------------------------------
// Kernel 2: final 7->7 3x3 SAME conv, fp32 (R1 config — measured 24.8 us).
// ---------------------------------------------------------------------------
__global__ __launch_bounds__(256, 4) void mix_kernel(
    const float* __restrict__ Wm, const float* __restrict__ bm,
    float* __restrict__ out)
{
    __shared__ float Wms[7 * 7 * 9];
    __shared__ float bms[7];

    const int tid = threadIdx.y * 64 + threadIdx.x;
    for (int i = tid; i < 7 * 7 * 9; i += 256) Wms[i] = Wm[i];
    if (tid < 7) bms[tid] = bm[tid];
    __syncthreads();

    const int b  = blockIdx.y;
    const int h  = blockIdx.x * 4 + threadIdx.y;
    const int w0 = threadIdx.x * PX;

    float acc[7][PX];
    #pragma unroll
    for (int o = 0; o < 7; o++) {
        const float bv = bms[o];
        #pragma unroll
        for (int p = 0; p < PX; p++) acc[o][p] = bv;
    }

    #pragma unroll 1
    for (int ic = 0; ic < 7; ic++) {
        const float* xp = g_comb + ((size_t)(b * CHn + ic)) * Hn * Wn;
        float win[3][PX + 2];
        #pragma unroll
        for (int r = 0; r < 3; r++) {
            int hh = h - 1 + r;
            bool hok = (hh >= 0) && (hh < Hn);
            #pragma unroll
            for (int c = 0; c < PX + 2; c++) {
                int ww = w0 - 1 + c;
                win[r][c] = (hok && ww >= 0 && ww < Wn) ? xp[hh * Wn + ww] : 0.f;
            }
        }
        #pragma unroll
        for (int o = 0; o < 7; o++) {
            #pragma unroll
            for (int kh = 0; kh < 3; kh++) {
                #pragma unroll
                for (int kw = 0; kw < 3; kw++) {
                    const float wv = Wms[(o * 7 + ic) * 9 + kh * 3 + kw];
                    #pragma unroll
                    for (int p = 0; p < PX; p++)
                        acc[o][p] = fmaf(wv, win[kh][kw + p], acc[o][p]);
                }
            }
        }
    }

    #pragma unroll
    for (int o = 0; o < 7; o++) {
        float4 v = make_float4(acc[o][0], acc[o][1], acc[o][2], acc[o][3]);
        *(float4*)(out + (((size_t)(b * CHn + o)) * Hn + h) * Wn + w0) = v;
    }
}

// ---------------------------------------------------------------------------
// kernel_launch: graph-capturable, allocation-free.
// Input order (metadata): x, W1, b1, W2, b2, Wm, bm
// ---------------------------------------------------------------------------
extern "C" void kernel_launch(void* const* d_in, const int* in_sizes, int n_in,
                              void* d_out, int out_size)
{
    const float* x  = (const float*)d_in[0];
    const float* W1 = (const float*)d_in[1];
    const float* b1 = (const float*)d_in[2];
    const float* W2 = (const float*)d_in[3];
    const float* b2 = (const float*)d_in[4];
    const float* Wm = (const float*)d_in[5];
    const float* bm = (const float*)d_in[6];
    float* out = (float*)d_out;

    dim3 gridB(CTAS_PER_BRANCH, NBR, 1);
    branch_kernel<<<gridB, 128>>>(x, W1, b1, W2, b2);

    dim3 blockM(64, 4, 1);
    dim3 gridM(Hn / 4, Bn, 1);
    mix_kernel<<<gridM, blockM>>>(Wm, bm, out);
}

// round 12
// speedup vs baseline: 1.5172x; 1.5172x over previous
#include <cuda_runtime.h>
#include <cuda_fp16.h>
#include <cstdint>

#define Bn   8
#define CHn  7
#define Hn   256
#define Wn   256
#define NBR  6
#define C1   64
#define PX   4

#define CTAS_PER_BRANCH 1024
#define ITERS           8      // 1024 CTAs * 4 warps * 16 px * 8 iters = 524288 px

// Scratch for the "combined" (B,7,H,W) tensor between the two kernels.
__device__ float g_comb[Bn * CHn * Hn * Wn];

__device__ __forceinline__ uint32_t smem_u32(const void* p) {
    uint32_t a;
    asm("{ .reg .u64 t; cvta.to.shared.u64 t, %1; cvt.u32.u64 %0, t; }" : "=r"(a) : "l"(p));
    return a;
}
__device__ __forceinline__ unsigned packh2(float lo, float hi) {
    __half2 h = __floats2half2_rn(lo, hi);
    return *reinterpret_cast<unsigned*>(&h);
}
__device__ __forceinline__ void ldmatrix_x4(uint32_t r[4], uint32_t addr) {
    asm volatile("ldmatrix.sync.aligned.m8n8.x4.shared.b16 {%0,%1,%2,%3}, [%4];"
                 : "=r"(r[0]), "=r"(r[1]), "=r"(r[2]), "=r"(r[3]) : "r"(addr));
}
__device__ __forceinline__ void ldmatrix_x2(uint32_t r[2], uint32_t addr) {
    asm volatile("ldmatrix.sync.aligned.m8n8.x2.shared.b16 {%0,%1}, [%2];"
                 : "=r"(r[0]), "=r"(r[1]) : "r"(addr));
}
__device__ __forceinline__ void mma16816(float c[4], const uint32_t a[4], const uint32_t b[2]) {
    asm volatile(
        "mma.sync.aligned.m16n8k16.row.col.f32.f16.f16.f32 "
        "{%0,%1,%2,%3}, {%4,%5,%6,%7}, {%8,%9}, {%0,%1,%2,%3};"
        : "+f"(c[0]), "+f"(c[1]), "+f"(c[2]), "+f"(c[3])
        : "r"(a[0]), "r"(a[1]), "r"(a[2]), "r"(a[3]), "r"(b[0]), "r"(b[1]));
}

// Load one 3x3 window (zero-padded); interior path is unpredicated.
__device__ __forceinline__ void load_win(const float* __restrict__ xs,
                                         int hh0, int ww0, bool interior,
                                         float win[9])
{
    if (interior) {
        const float* pr = xs + (hh0 - 1) * Wn + (ww0 - 1);
        win[0] = __ldg(pr);          win[1] = __ldg(pr + 1);          win[2] = __ldg(pr + 2);
        win[3] = __ldg(pr + Wn);     win[4] = __ldg(pr + Wn + 1);     win[5] = __ldg(pr + Wn + 2);
        win[6] = __ldg(pr + 2 * Wn); win[7] = __ldg(pr + 2 * Wn + 1); win[8] = __ldg(pr + 2 * Wn + 2);
    } else {
        #pragma unroll
        for (int r = 0; r < 3; r++) {
            int hh = hh0 - 1 + r;
            bool hok = (hh >= 0) && (hh < Hn);
            #pragma unroll
            for (int cc = 0; cc < 3; cc++) {
                int ww = ww0 - 1 + cc;
                bool ok = hok && (ww >= 0) && (ww < Wn);
                win[r * 3 + cc] = ok ? __ldg(&xs[hh * Wn + ww]) : 0.f;
            }
        }
    }
}

// ---------------------------------------------------------------------------
// Branch kernel: warp-level HMMA implicit GEMM with software-pipelined LDG.
// A[16 px, 32 k] fp16: k0-8 base taps, k9 = 1.0 (bias lane), k10-15 = 0,
//                      k16-24 check taps, k25-31 = 0.
// B[64 ch, 32 k] fp16: k0-8 W1 base taps, k9 = b1[c], k16-24 W1 check taps.
// D fp32. Epilogue: relu, tree dot w2, quad-reduce, +b2, sigmoid, weight, store.
// Row stride 40 halves (80B): conflict-free ldmatrix. A double-buffered.
// Next iteration's 9 LDGs issue right after this iteration's ldmatrix, so
// L2 latency overlaps HMMA + epilogue instead of heading the critical path.
// ---------------------------------------------------------------------------
__global__ __launch_bounds__(128) void branch_kernel(
    const float* __restrict__ x,
    const float* __restrict__ W1, const float* __restrict__ b1,
    const float* __restrict__ W2, const float* __restrict__ b2)
{
    __shared__ __half Bs[C1 * 40];           // 5120 B
    __shared__ __half As[4][2][16 * 40];     // 4 warps x 2 buffers x 1280 B
    __shared__ float  w2s[C1];
    __shared__ float  sb2v;

    const int tid  = threadIdx.x;
    const int warp = tid >> 5;
    const int lane = tid & 31;
    const int n    = blockIdx.y;
    const int base_ic = (n < 3) ? 0 : 1;
    const int srcch   = (n < 3) ? n : n + 1;

    // ---- stage B (reordered, fp16) + w2 + b2 ----
    for (int i = tid; i < C1 * 40; i += 128) Bs[i] = __ushort_as_half(0);
    __syncthreads();
    for (int i = tid; i < C1 * 9; i += 128) {
        int c = i / 9, k = i % 9;
        Bs[c * 40 + k]      = __float2half_rn(W1[(((n * C1 + c) * 2 + base_ic) * 9) + k]);
        Bs[c * 40 + 16 + k] = __float2half_rn(W1[(((n * C1 + c) * 2 + (1 - base_ic)) * 9) + k]);
    }
    for (int c = tid; c < C1; c += 128) {
        Bs[c * 40 + 9] = __float2half_rn(b1[n * C1 + c]);
        w2s[c] = W2[n * C1 + c];
    }
    if (tid == 0) sb2v = b2[n];
    __syncthreads();

    // ---- load B fragments into registers (kept for whole kernel) ----
    uint32_t bf[8][2][2];
    {
        const uint32_t bbase = smem_u32(Bs);
        #pragma unroll
        for (int j = 0; j < 8; j++)
            #pragma unroll
            for (int s = 0; s < 2; s++) {
                int row = 8 * j + (lane & 7);
                uint32_t addr = bbase + (uint32_t)(row * 40 + s * 16) * 2
                              + (uint32_t)(((lane >> 3) & 1) * 16);
                ldmatrix_x2(bf[j][s], addr);
            }
    }
    // per-thread w2 values for owned columns
    float w2a[8], w2b[8];
    #pragma unroll
    for (int j = 0; j < 8; j++) {
        int n0 = 8 * j + 2 * (lane & 3);
        w2a[j] = w2s[n0];
        w2b[j] = w2s[n0 + 1];
    }
    const float my_b2 = sb2v;

    const int p  = lane >> 1;                  // pixel within tile (2 threads/px)
    const int ch = (lane & 1) ? srcch : 3;     // even: base ch, odd: check ch
    const int g  = lane >> 2;

    // ---- prologue: load iter-0 window ----
    float win[9];
    {
        const int pixbase = (blockIdx.x * 4 + warp) * 16;
        const int pix = pixbase + p;
        const int b   = pix >> 16;
        const int hh0 = (pix >> 8) & 255;
        const int ww0 = pix & 255;
        const int tile_w = (pixbase >> 4) & 15;
        const bool interior = (hh0 >= 1) && (hh0 <= 254) && (tile_w >= 1) && (tile_w <= 14);
        const float* xs = x + ((size_t)(b * CHn + ch) << 16);
        load_win(xs, hh0, ww0, interior, win);
    }

    for (int it = 0; it < ITERS; it++) {
        const int pixbase = ((blockIdx.x + it * CTAS_PER_BRANCH) * 4 + warp) * 16;
        const int buf = it & 1;
        const uint32_t abase = smem_u32(&As[warp][buf][0]);

        // ---- pack current window -> STS into A tile ----
        unsigned hv0 = packh2(win[0], win[1]);
        unsigned hv1 = packh2(win[2], win[3]);
        unsigned hv2 = packh2(win[4], win[5]);
        unsigned hv3 = packh2(win[6], win[7]);
        unsigned hv4 = packh2(win[8], (lane & 1) ? 0.f : 1.0f);  // even gets bias lane k9
        {
            __half* Arow = &As[warp][buf][p * 40 + (lane & 1) * 16];
            *reinterpret_cast<uint4*>(Arow)     = make_uint4(hv0, hv1, hv2, hv3);
            *reinterpret_cast<uint4*>(Arow + 8) = make_uint4(hv4, 0u, 0u, 0u);
        }

        // center values via shuffle (producer: lane 2*row+{0,1})
        float cenC0 = __shfl_sync(0xFFFFFFFFu, win[4], (g << 1) | 1);
        float cenC1 = __shfl_sync(0xFFFFFFFFu, win[4], ((g + 8) << 1) | 1);
        float cenB0 = 0.f, cenB1 = 0.f;
        if (n == 0) {
            cenB0 = __shfl_sync(0xFFFFFFFFu, win[4], g << 1);
            cenB1 = __shfl_sync(0xFFFFFFFFu, win[4], (g + 8) << 1);
        }
        __syncwarp();

        // ---- A fragments ----
        uint32_t a0[4], a1[4];
        {
            int row = lane & 15;
            uint32_t addr = abase + (uint32_t)(row * 40) * 2 + (uint32_t)((lane >> 4) * 16);
            ldmatrix_x4(a0, addr);        // k 0..15
            ldmatrix_x4(a1, addr + 32);   // k 16..31
        }

        // ---- prefetch next iteration's window (overlaps MMA + epilogue) ----
        if (it + 1 < ITERS) {
            const int pbN = ((blockIdx.x + (it + 1) * CTAS_PER_BRANCH) * 4 + warp) * 16;
            const int pixN = pbN + p;
            const int bN   = pixN >> 16;
            const int hh0N = (pixN >> 8) & 255;
            const int ww0N = pixN & 255;
            const int tile_wN = (pbN >> 4) & 15;
            const bool interiorN = (hh0N >= 1) && (hh0N <= 254) && (tile_wN >= 1) && (tile_wN <= 14);
            const float* xsN = x + ((size_t)(bN * CHn + ch) << 16);
            load_win(xsN, hh0N, ww0N, interiorN, win);
        }

        // ---- 16 HMMA ----
        float c[8][4];
        #pragma unroll
        for (int j = 0; j < 8; j++) {
            c[j][0] = c[j][1] = c[j][2] = c[j][3] = 0.f;
            mma16816(c[j], a0, bf[j][0]);
            mma16816(c[j], a1, bf[j][1]);
        }

        // ---- epilogue: relu + w2 dot, 8 independent 4-deep chains ----
        float pa0 = 0.f, pa1 = 0.f, qa0 = 0.f, qa1 = 0.f;
        float pb0 = 0.f, pb1 = 0.f, qb0 = 0.f, qb1 = 0.f;
        #pragma unroll
        for (int j = 0; j < 8; j++) {
            float r0 = fmaxf(c[j][0], 0.f), r1 = fmaxf(c[j][1], 0.f);
            float r2 = fmaxf(c[j][2], 0.f), r3 = fmaxf(c[j][3], 0.f);
            if (j & 1) {
                pa1 = fmaf(w2a[j], r0, pa1); qa1 = fmaf(w2b[j], r1, qa1);
                pb1 = fmaf(w2a[j], r2, pb1); qb1 = fmaf(w2b[j], r3, qb1);
            } else {
                pa0 = fmaf(w2a[j], r0, pa0); qa0 = fmaf(w2b[j], r1, qa0);
                pb0 = fmaf(w2a[j], r2, pb0); qb0 = fmaf(w2b[j], r3, qb0);
            }
        }
        float simA = (pa0 + qa0) + (pa1 + qa1);
        float simB = (pb0 + qb0) + (pb1 + qb1);
        simA += __shfl_xor_sync(0xFFFFFFFFu, simA, 1);
        simB += __shfl_xor_sync(0xFFFFFFFFu, simB, 1);
        simA += __shfl_xor_sync(0xFFFFFFFFu, simA, 2);
        simB += __shfl_xor_sync(0xFFFFFFFFu, simB, 2);

        if ((lane & 3) == 0) {
            int pixA = pixbase + g;
            int pixB = pixbase + g + 8;
            float resA = cenC0 / (1.f + __expf(-(simA + my_b2)));
            float resB = cenC1 / (1.f + __expf(-(simB + my_b2)));
            int bA = pixA >> 16, hwA = pixA & 65535;
            int bB = pixB >> 16, hwB = pixB & 65535;
            g_comb[((size_t)(bA * CHn + srcch) << 16) + hwA] = resA;
            g_comb[((size_t)(bB * CHn + srcch) << 16) + hwB] = resB;
            if (n == 0) {
                g_comb[((size_t)(bA * CHn + 3) << 16) + hwA] = cenB0;
                g_comb[((size_t)(bB * CHn + 3) << 16) + hwB] = cenB1;
            }
        }
    }
}

// ---------------------------------------------------------------------------
// Kernel 2: final 7->7 3x3 SAME conv, fp32 (R1 config — 24.8 us at R8 clocks).
// ---------------------------------------------------------------------------
__global__ __launch_bounds__(256, 4) void mix_kernel(
    const float* __restrict__ Wm, const float* __restrict__ bm,
    float* __restrict__ out)
{
    __shared__ float Wms[7 * 7 * 9];
    __shared__ float bms[7];

    const int tid = threadIdx.y * 64 + threadIdx.x;
    for (int i = tid; i < 7 * 7 * 9; i += 256) Wms[i] = Wm[i];
    if (tid < 7) bms[tid] = bm[tid];
    __syncthreads();

    const int b  = blockIdx.y;
    const int h  = blockIdx.x * 4 + threadIdx.y;
    const int w0 = threadIdx.x * PX;

    float acc[7][PX];
    #pragma unroll
    for (int o = 0; o < 7; o++) {
        const float bv = bms[o];
        #pragma unroll
        for (int p = 0; p < PX; p++) acc[o][p] = bv;
    }

    #pragma unroll 1
    for (int ic = 0; ic < 7; ic++) {
        const float* xp = g_comb + ((size_t)(b * CHn + ic)) * Hn * Wn;
        float win[3][PX + 2];
        #pragma unroll
        for (int r = 0; r < 3; r++) {
            int hh = h - 1 + r;
            bool hok = (hh >= 0) && (hh < Hn);
            #pragma unroll
            for (int c = 0; c < PX + 2; c++) {
                int ww = w0 - 1 + c;
                win[r][c] = (hok && ww >= 0 && ww < Wn) ? xp[hh * Wn + ww] : 0.f;
            }
        }
        #pragma unroll
        for (int o = 0; o < 7; o++) {
            #pragma unroll
            for (int kh = 0; kh < 3; kh++) {
                #pragma unroll
                for (int kw = 0; kw < 3; kw++) {
                    const float wv = Wms[(o * 7 + ic) * 9 + kh * 3 + kw];
                    #pragma unroll
                    for (int p = 0; p < PX; p++)
                        acc[o][p] = fmaf(wv, win[kh][kw + p], acc[o][p]);
                }
            }
        }
    }

    #pragma unroll
    for (int o = 0; o < 7; o++) {
        float4 v = make_float4(acc[o][0], acc[o][1], acc[o][2], acc[o][3]);
        *(float4*)(out + (((size_t)(b * CHn + o)) * Hn + h) * Wn + w0) = v;
    }
}

// ---------------------------------------------------------------------------
// kernel_launch: graph-capturable, allocation-free.
// Input order (metadata): x, W1, b1, W2, b2, Wm, bm
// ---------------------------------------------------------------------------
extern "C" void kernel_launch(void* const* d_in, const int* in_sizes, int n_in,
                              void* d_out, int out_size)
{
    const float* x  = (const float*)d_in[0];
    const float* W1 = (const float*)d_in[1];
    const float* b1 = (const float*)d_in[2];
    const float* W2 = (const float*)d_in[3];
    const float* b2 = (const float*)d_in[4];
    const float* Wm = (const float*)d_in[5];
    const float* bm = (const float*)d_in[6];
    float* out = (float*)d_out;

    dim3 gridB(CTAS_PER_BRANCH, NBR, 1);
    branch_kernel<<<gridB, 128>>>(x, W1, b1, W2, b2);

    dim3 blockM(64, 4, 1);
    dim3 gridM(Hn / 4, Bn, 1);
    mix_kernel<<<gridM, blockM>>>(Wm, bm, out);
}

// round 13
// speedup vs baseline: 1.7135x; 1.1294x over previous
#include <cuda_runtime.h>
#include <cuda_fp16.h>
#include <cstdint>

#define Bn   8
#define CHn  7
#define Hn   256
#define Wn   256
#define NBR  6
#define C1   64
#define PX   4

#define CTAS_PER_BRANCH 1024
#define ITERS           8      // 1024 CTAs * 4 warps * 16 px * 8 iters = 524288 px

// Scratch for the "combined" (B,7,H,W) tensor between the two kernels.
__device__ float g_comb[Bn * CHn * Hn * Wn];

__device__ __forceinline__ uint32_t smem_u32(const void* p) {
    uint32_t a;
    asm("{ .reg .u64 t; cvta.to.shared.u64 t, %1; cvt.u32.u64 %0, t; }" : "=r"(a) : "l"(p));
    return a;
}
__device__ __forceinline__ unsigned packh2(float lo, float hi) {
    __half2 h = __floats2half2_rn(lo, hi);
    return *reinterpret_cast<unsigned*>(&h);
}
__device__ __forceinline__ void ldmatrix_x4(uint32_t r[4], uint32_t addr) {
    asm volatile("ldmatrix.sync.aligned.m8n8.x4.shared.b16 {%0,%1,%2,%3}, [%4];"
                 : "=r"(r[0]), "=r"(r[1]), "=r"(r[2]), "=r"(r[3]) : "r"(addr));
}
__device__ __forceinline__ void ldmatrix_x2(uint32_t r[2], uint32_t addr) {
    asm volatile("ldmatrix.sync.aligned.m8n8.x2.shared.b16 {%0,%1}, [%2];"
                 : "=r"(r[0]), "=r"(r[1]) : "r"(addr));
}
// fp16-accumulator MMA: C/D are 2 regs = 4 halves.
__device__ __forceinline__ void mma16816_h(uint32_t c[2], const uint32_t a[4], const uint32_t b[2]) {
    asm volatile(
        "mma.sync.aligned.m16n8k16.row.col.f16.f16.f16.f16 "
        "{%0,%1}, {%2,%3,%4,%5}, {%6,%7}, {%0,%1};"
        : "+r"(c[0]), "+r"(c[1])
        : "r"(a[0]), "r"(a[1]), "r"(a[2]), "r"(a[3]), "r"(b[0]), "r"(b[1]));
}

// Load one 3x3 window (zero-padded); interior path is unpredicated.
__device__ __forceinline__ void load_win(const float* __restrict__ xs,
                                         int hh0, int ww0, bool interior,
                                         float win[9])
{
    if (interior) {
        const float* pr = xs + (hh0 - 1) * Wn + (ww0 - 1);
        win[0] = __ldg(pr);          win[1] = __ldg(pr + 1);          win[2] = __ldg(pr + 2);
        win[3] = __ldg(pr + Wn);     win[4] = __ldg(pr + Wn + 1);     win[5] = __ldg(pr + Wn + 2);
        win[6] = __ldg(pr + 2 * Wn); win[7] = __ldg(pr + 2 * Wn + 1); win[8] = __ldg(pr + 2 * Wn + 2);
    } else {
        #pragma unroll
        for (int r = 0; r < 3; r++) {
            int hh = hh0 - 1 + r;
            bool hok = (hh >= 0) && (hh < Hn);
            #pragma unroll
            for (int cc = 0; cc < 3; cc++) {
                int ww = ww0 - 1 + cc;
                bool ok = hok && (ww >= 0) && (ww < Wn);
                win[r * 3 + cc] = ok ? __ldg(&xs[hh * Wn + ww]) : 0.f;
            }
        }
    }
}

// ---------------------------------------------------------------------------
// Branch kernel: warp-level HMMA implicit GEMM, fp16 accumulators.
// A[16 px, 32 k] fp16: k0-8 base taps, k9 = 1.0 (bias lane), k10-15 = 0,
//                      k16-24 check taps, k25-31 = 0.
// B[64 ch, 32 k] fp16: k0-8 W1 base taps, k9 = b1[c], k16-24 W1 check taps.
// D fp16 (half2 frags). Epilogue: hmax2 relu + hfma2 w2 dot, quad-reduce,
// +b2, sigmoid, weight, store. Row stride 40 halves: conflict-free ldmatrix.
// A double-buffered; next iter's LDGs prefetched past the MMA.
// ---------------------------------------------------------------------------
__global__ __launch_bounds__(128) void branch_kernel(
    const float* __restrict__ x,
    const float* __restrict__ W1, const float* __restrict__ b1,
    const float* __restrict__ W2, const float* __restrict__ b2)
{
    __shared__ __half Bs[C1 * 40];           // 5120 B
    __shared__ __half As[4][2][16 * 40];     // 4 warps x 2 buffers x 1280 B
    __shared__ float  w2s[C1];
    __shared__ float  sb2v;

    const int tid  = threadIdx.x;
    const int warp = tid >> 5;
    const int lane = tid & 31;
    const int n    = blockIdx.y;
    const int base_ic = (n < 3) ? 0 : 1;
    const int srcch   = (n < 3) ? n : n + 1;

    // ---- stage B (reordered, fp16) + w2 + b2 ----
    for (int i = tid; i < C1 * 40; i += 128) Bs[i] = __ushort_as_half(0);
    __syncthreads();
    for (int i = tid; i < C1 * 9; i += 128) {
        int c = i / 9, k = i % 9;
        Bs[c * 40 + k]      = __float2half_rn(W1[(((n * C1 + c) * 2 + base_ic) * 9) + k]);
        Bs[c * 40 + 16 + k] = __float2half_rn(W1[(((n * C1 + c) * 2 + (1 - base_ic)) * 9) + k]);
    }
    for (int c = tid; c < C1; c += 128) {
        Bs[c * 40 + 9] = __float2half_rn(b1[n * C1 + c]);
        w2s[c] = W2[n * C1 + c];
    }
    if (tid == 0) sb2v = b2[n];
    __syncthreads();

    // ---- load B fragments into registers (kept for whole kernel) ----
    uint32_t bf[8][2][2];
    {
        const uint32_t bbase = smem_u32(Bs);
        #pragma unroll
        for (int j = 0; j < 8; j++)
            #pragma unroll
            for (int s = 0; s < 2; s++) {
                int row = 8 * j + (lane & 7);
                uint32_t addr = bbase + (uint32_t)(row * 40 + s * 16) * 2
                              + (uint32_t)(((lane >> 3) & 1) * 16);
                ldmatrix_x2(bf[j][s], addr);
            }
    }
    // per-thread w2 pairs (half2) for owned columns
    unsigned w2h[8];
    #pragma unroll
    for (int j = 0; j < 8; j++) {
        int n0 = 8 * j + 2 * (lane & 3);
        w2h[j] = packh2(w2s[n0], w2s[n0 + 1]);
    }
    const float my_b2 = sb2v;

    const int p  = lane >> 1;                  // pixel within tile (2 threads/px)
    const int ch = (lane & 1) ? srcch : 3;     // even: base ch, odd: check ch
    const int g  = lane >> 2;

    // ---- prologue: load iter-0 window ----
    float win[9];
    {
        const int pixbase = (blockIdx.x * 4 + warp) * 16;
        const int pix = pixbase + p;
        const int b   = pix >> 16;
        const int hh0 = (pix >> 8) & 255;
        const int ww0 = pix & 255;
        const int tile_w = (pixbase >> 4) & 15;
        const bool interior = (hh0 >= 1) && (hh0 <= 254) && (tile_w >= 1) && (tile_w <= 14);
        const float* xs = x + ((size_t)(b * CHn + ch) << 16);
        load_win(xs, hh0, ww0, interior, win);
    }

    for (int it = 0; it < ITERS; it++) {
        const int pixbase = ((blockIdx.x + it * CTAS_PER_BRANCH) * 4 + warp) * 16;
        const int buf = it & 1;
        const uint32_t abase = smem_u32(&As[warp][buf][0]);

        // ---- pack current window -> STS into A tile ----
        unsigned hv0 = packh2(win[0], win[1]);
        unsigned hv1 = packh2(win[2], win[3]);
        unsigned hv2 = packh2(win[4], win[5]);
        unsigned hv3 = packh2(win[6], win[7]);
        unsigned hv4 = packh2(win[8], (lane & 1) ? 0.f : 1.0f);  // even gets bias lane k9
        {
            __half* Arow = &As[warp][buf][p * 40 + (lane & 1) * 16];
            *reinterpret_cast<uint4*>(Arow)     = make_uint4(hv0, hv1, hv2, hv3);
            *reinterpret_cast<uint4*>(Arow + 8) = make_uint4(hv4, 0u, 0u, 0u);
        }

        // center values via shuffle (producer: lane 2*row+{0,1})
        float cenC0 = __shfl_sync(0xFFFFFFFFu, win[4], (g << 1) | 1);
        float cenC1 = __shfl_sync(0xFFFFFFFFu, win[4], ((g + 8) << 1) | 1);
        float cenB0 = 0.f, cenB1 = 0.f;
        if (n == 0) {
            cenB0 = __shfl_sync(0xFFFFFFFFu, win[4], g << 1);
            cenB1 = __shfl_sync(0xFFFFFFFFu, win[4], (g + 8) << 1);
        }
        __syncwarp();

        // ---- A fragments ----
        uint32_t a0[4], a1[4];
        {
            int row = lane & 15;
            uint32_t addr = abase + (uint32_t)(row * 40) * 2 + (uint32_t)((lane >> 4) * 16);
            ldmatrix_x4(a0, addr);        // k 0..15
            ldmatrix_x4(a1, addr + 32);   // k 16..31
        }

        // ---- prefetch next iteration's window (overlaps MMA + epilogue) ----
        if (it + 1 < ITERS) {
            const int pbN = ((blockIdx.x + (it + 1) * CTAS_PER_BRANCH) * 4 + warp) * 16;
            const int pixN = pbN + p;
            const int bN   = pixN >> 16;
            const int hh0N = (pixN >> 8) & 255;
            const int ww0N = pixN & 255;
            const int tile_wN = (pbN >> 4) & 15;
            const bool interiorN = (hh0N >= 1) && (hh0N <= 254) && (tile_wN >= 1) && (tile_wN <= 14);
            const float* xsN = x + ((size_t)(bN * CHn + ch) << 16);
            load_win(xsN, hh0N, ww0N, interiorN, win);
        }

        // ---- 16 HMMA (fp16 accum) ----
        uint32_t c[8][2];
        #pragma unroll
        for (int j = 0; j < 8; j++) {
            c[j][0] = 0u; c[j][1] = 0u;
            mma16816_h(c[j], a0, bf[j][0]);
            mma16816_h(c[j], a1, bf[j][1]);
        }

        // ---- epilogue: half2 relu + w2 dot, 2 chains per row-half ----
        const __half2 zero2 = __floats2half2_rn(0.f, 0.f);
        __half2 aA0 = zero2, aA1 = zero2, aB0 = zero2, aB1 = zero2;
        #pragma unroll
        for (int j = 0; j < 8; j++) {
            __half2 w2v = *reinterpret_cast<__half2*>(&w2h[j]);
            __half2 rA = __hmax2(*reinterpret_cast<__half2*>(&c[j][0]), zero2);
            __half2 rB = __hmax2(*reinterpret_cast<__half2*>(&c[j][1]), zero2);
            if (j & 1) { aA1 = __hfma2(w2v, rA, aA1); aB1 = __hfma2(w2v, rB, aB1); }
            else       { aA0 = __hfma2(w2v, rA, aA0); aB0 = __hfma2(w2v, rB, aB0); }
        }
        float2 fA0 = __half22float2(aA0), fA1 = __half22float2(aA1);
        float2 fB0 = __half22float2(aB0), fB1 = __half22float2(aB1);
        float simA = (fA0.x + fA0.y) + (fA1.x + fA1.y);
        float simB = (fB0.x + fB0.y) + (fB1.x + fB1.y);
        simA += __shfl_xor_sync(0xFFFFFFFFu, simA, 1);
        simB += __shfl_xor_sync(0xFFFFFFFFu, simB, 1);
        simA += __shfl_xor_sync(0xFFFFFFFFu, simA, 2);
        simB += __shfl_xor_sync(0xFFFFFFFFu, simB, 2);

        if ((lane & 3) == 0) {
            int pixA = pixbase + g;
            int pixB = pixbase + g + 8;
            float resA = cenC0 / (1.f + __expf(-(simA + my_b2)));
            float resB = cenC1 / (1.f + __expf(-(simB + my_b2)));
            int bA = pixA >> 16, hwA = pixA & 65535;
            int bB = pixB >> 16, hwB = pixB & 65535;
            g_comb[((size_t)(bA * CHn + srcch) << 16) + hwA] = resA;
            g_comb[((size_t)(bB * CHn + srcch) << 16) + hwB] = resB;
            if (n == 0) {
                g_comb[((size_t)(bA * CHn + 3) << 16) + hwA] = cenB0;
                g_comb[((size_t)(bB * CHn + 3) << 16) + hwB] = cenB1;
            }
        }
    }
}

// ---------------------------------------------------------------------------
// Kernel 2: final 7->7 3x3 SAME conv, fp32 (R1 config — 24.8 us at R8 clocks).
// ---------------------------------------------------------------------------
__global__ __launch_bounds__(256, 4) void mix_kernel(
    const float* __restrict__ Wm, const float* __restrict__ bm,
    float* __restrict__ out)
{
    __shared__ float Wms[7 * 7 * 9];
    __shared__ float bms[7];

    const int tid = threadIdx.y * 64 + threadIdx.x;
    for (int i = tid; i < 7 * 7 * 9; i += 256) Wms[i] = Wm[i];
    if (tid < 7) bms[tid] = bm[tid];
    __syncthreads();

    const int b  = blockIdx.y;
    const int h  = blockIdx.x * 4 + threadIdx.y;
    const int w0 = threadIdx.x * PX;

    float acc[7][PX];
    #pragma unroll
    for (int o = 0; o < 7; o++) {
        const float bv = bms[o];
        #pragma unroll
        for (int p = 0; p < PX; p++) acc[o][p] = bv;
    }

    #pragma unroll 1
    for (int ic = 0; ic < 7; ic++) {
        const float* xp = g_comb + ((size_t)(b * CHn + ic)) * Hn * Wn;
        float win[3][PX + 2];
        #pragma unroll
        for (int r = 0; r < 3; r++) {
            int hh = h - 1 + r;
            bool hok = (hh >= 0) && (hh < Hn);
            #pragma unroll
            for (int c = 0; c < PX + 2; c++) {
                int ww = w0 - 1 + c;
                win[r][c] = (hok && ww >= 0 && ww < Wn) ? xp[hh * Wn + ww] : 0.f;
            }
        }
        #pragma unroll
        for (int o = 0; o < 7; o++) {
            #pragma unroll
            for (int kh = 0; kh < 3; kh++) {
                #pragma unroll
                for (int kw = 0; kw < 3; kw++) {
                    const float wv = Wms[(o * 7 + ic) * 9 + kh * 3 + kw];
                    #pragma unroll
                    for (int p = 0; p < PX; p++)
                        acc[o][p] = fmaf(wv, win[kh][kw + p], acc[o][p]);
                }
            }
        }
    }

    #pragma unroll
    for (int o = 0; o < 7; o++) {
        float4 v = make_float4(acc[o][0], acc[o][1], acc[o][2], acc[o][3]);
        *(float4*)(out + (((size_t)(b * CHn + o)) * Hn + h) * Wn + w0) = v;
    }
}

// ---------------------------------------------------------------------------
// kernel_launch: graph-capturable, allocation-free.
// Input order (metadata): x, W1, b1, W2, b2, Wm, bm
// ---------------------------------------------------------------------------
extern "C" void kernel_launch(void* const* d_in, const int* in_sizes, int n_in,
                              void* d_out, int out_size)
{
    const float* x  = (const float*)d_in[0];
    const float* W1 = (const float*)d_in[1];
    const float* b1 = (const float*)d_in[2];
    const float* W2 = (const float*)d_in[3];
    const float* b2 = (const float*)d_in[4];
    const float* Wm = (const float*)d_in[5];
    const float* bm = (const float*)d_in[6];
    float* out = (float*)d_out;

    dim3 gridB(CTAS_PER_BRANCH, NBR, 1);
    branch_kernel<<<gridB, 128>>>(x, W1, b1, W2, b2);

    dim3 blockM(64, 4, 1);
    dim3 gridM(Hn / 4, Bn, 1);
    mix_kernel<<<gridM, blockM>>>(Wm, bm, out);
}